// round 2
// baseline (speedup 1.0000x reference)
#include <cuda_runtime.h>

// Fixed shapes: z_e [16,2048,512] -> N=32768 rows, codebook [4096,512]
#define NROWS 32768
#define DIM   512
#define KC    4096

// Scratch (no allocations allowed -> __device__ globals)
__device__ float g_wnorm[KC];
__device__ float g_xnorm[NROWS];
__device__ int   g_k[NROWS];
__device__ float g_partial[NROWS];
__device__ int   g_used[KC];

// ---------------------------------------------------------------------------
__global__ void init_kernel() {
    int i = blockIdx.x * blockDim.x + threadIdx.x;
    if (i < KC) g_used[i] = 0;
}

// ---------------------------------------------------------------------------
// ||w||^2 per code, replicating XLA CPU sequential scalar reduce:
// acc = fl(acc + fl(w*w)), ascending d, NO fma.
__global__ void wnorm_kernel(const float* __restrict__ cb) {
    int code = blockIdx.x * blockDim.x + threadIdx.x;
    if (code >= KC) return;
    const float* p = cb + (size_t)code * DIM;
    float acc = 0.f;
    for (int d = 0; d < DIM; d++)
        acc = __fadd_rn(acc, __fmul_rn(p[d], p[d]));
    g_wnorm[code] = acc;
}

// ||x||^2 per row, same sequential no-fma order.
__global__ void xnorm_kernel(const float* __restrict__ z) {
    int row = blockIdx.x * blockDim.x + threadIdx.x;
    if (row >= NROWS) return;
    const float* p = z + (size_t)row * DIM;
    float acc = 0.f;
    for (int d = 0; d < DIM; d++)
        acc = __fadd_rn(acc, __fmul_rn(p[d], p[d]));
    g_xnorm[row] = acc;
}

// ---------------------------------------------------------------------------
// Fused fp32 GEMM + argmin.
// dot accumulated as a single FFMA chain in ascending-k order (bit-identical
// to Eigen's gebp microkernel chain). Score replicates the reference op order:
//   d = fl( fl(xnorm - fl(2*dot)) + wnorm )
// Argmin: strict <, ascending index (first occurrence, like jnp.argmin).
#define BM 128
#define BN 128
#define BK 16
#define TM 8
#define TN 8

__global__ void __launch_bounds__(256, 2)
vq_argmin_kernel(const float* __restrict__ A, const float* __restrict__ B) {
    __shared__ float As[BK][BM];
    __shared__ float Bs[BK][BN];
    __shared__ float s_val[BM][17];
    __shared__ int   s_idx[BM][17];

    const int tid = threadIdx.x;
    const int tx  = tid & 15;   // col group (8 codes)
    const int ty  = tid >> 4;   // row group (8 rows)
    const int rowBase = blockIdx.x * BM;

    float bestV = 3.4e38f;
    int   bestI = 0;

    for (int cbase = 0; cbase < KC; cbase += BN) {
        float acc[TM][TN];
        #pragma unroll
        for (int i = 0; i < TM; i++)
            #pragma unroll
            for (int j = 0; j < TN; j++) acc[i][j] = 0.f;

        for (int dk = 0; dk < DIM; dk += BK) {
            #pragma unroll
            for (int t = 0; t < 2; t++) {
                int s  = tid + t * 256;
                int m  = s >> 2;
                int c4 = (s & 3) * 4;
                float4 v = *reinterpret_cast<const float4*>(
                    &A[(size_t)(rowBase + m) * DIM + dk + c4]);
                As[c4 + 0][m] = v.x; As[c4 + 1][m] = v.y;
                As[c4 + 2][m] = v.z; As[c4 + 3][m] = v.w;
            }
            #pragma unroll
            for (int t = 0; t < 2; t++) {
                int s  = tid + t * 256;
                int n  = s >> 2;
                int c4 = (s & 3) * 4;
                float4 v = *reinterpret_cast<const float4*>(
                    &B[(size_t)(cbase + n) * DIM + dk + c4]);
                Bs[c4 + 0][n] = v.x; Bs[c4 + 1][n] = v.y;
                Bs[c4 + 2][n] = v.z; Bs[c4 + 3][n] = v.w;
            }
            __syncthreads();

            #pragma unroll
            for (int kk = 0; kk < BK; kk++) {
                float a[TM], b[TN];
                *(float4*)&a[0] = *(const float4*)&As[kk][ty * TM];
                *(float4*)&a[4] = *(const float4*)&As[kk][ty * TM + 4];
                *(float4*)&b[0] = *(const float4*)&Bs[kk][tx * TN];
                *(float4*)&b[4] = *(const float4*)&Bs[kk][tx * TN + 4];
                #pragma unroll
                for (int i = 0; i < TM; i++)
                    #pragma unroll
                    for (int j = 0; j < TN; j++)
                        acc[i][j] = __fmaf_rn(a[i], b[j], acc[i][j]);
            }
            __syncthreads();
        }

        // per-thread argmin over its 8 codes, reference rounding order
        #pragma unroll
        for (int i = 0; i < TM; i++) {
            float xn = g_xnorm[rowBase + ty * TM + i];
            float mv = 3.4e38f; int mi = 0;
            #pragma unroll
            for (int j = 0; j < TN; j++) {
                int   col = cbase + tx * TN + j;
                float p   = __fmul_rn(2.0f, acc[i][j]);
                float q   = __fsub_rn(xn, p);
                float sc  = __fadd_rn(q, g_wnorm[col]);
                if (sc < mv) { mv = sc; mi = col; }
            }
            s_val[ty * TM + i][tx] = mv;
            s_idx[ty * TM + i][tx] = mi;
        }
        __syncthreads();

        // merge across the 16 col-groups (ascending tx => ascending index)
        if (tid < BM) {
            #pragma unroll
            for (int j = 0; j < 16; j++) {
                float v = s_val[tid][j];
                if (v < bestV) { bestV = v; bestI = s_idx[tid][j]; }
            }
        }
        __syncthreads();
    }

    if (tid < BM) g_k[rowBase + tid] = bestI;
}

// ---------------------------------------------------------------------------
// Gather z_q, emit straight-through output x + (z_q - x) (same fp ops as JAX),
// per-row loss partial, used flags, and k as float.
__global__ void gather_kernel(const float* __restrict__ z,
                              const float* __restrict__ cb,
                              float* __restrict__ out) {
    __shared__ float red[128];
    int row = blockIdx.x;
    int t   = threadIdx.x;
    int k   = g_k[row];

    float4 w = reinterpret_cast<const float4*>(cb + (size_t)k   * DIM)[t];
    float4 x = reinterpret_cast<const float4*>(z  + (size_t)row * DIM)[t];

    float4 o;
    o.x = __fadd_rn(x.x, __fsub_rn(w.x, x.x));
    o.y = __fadd_rn(x.y, __fsub_rn(w.y, x.y));
    o.z = __fadd_rn(x.z, __fsub_rn(w.z, x.z));
    o.w = __fadd_rn(x.w, __fsub_rn(w.w, x.w));
    reinterpret_cast<float4*>(out + (size_t)row * DIM)[t] = o;

    float dx = __fsub_rn(x.x, w.x), dy = __fsub_rn(x.y, w.y);
    float dz = __fsub_rn(x.z, w.z), dw = __fsub_rn(x.w, w.w);
    red[t] = dx * dx + dy * dy + dz * dz + dw * dw;
    __syncthreads();
    #pragma unroll
    for (int off = 64; off > 0; off >>= 1) {
        if (t < off) red[t] += red[t + off];
        __syncthreads();
    }
    if (t == 0) {
        g_partial[row] = red[0];
        g_used[k] = 1;
        out[(size_t)NROWS * DIM + row] = (float)k;   // k segment
    }
}

// ---------------------------------------------------------------------------
__global__ void finalize_kernel(float* __restrict__ out) {
    __shared__ double red[1024];
    int t = threadIdx.x;

    double s = 0.0;
    for (int i = t; i < NROWS; i += 1024) s += (double)g_partial[i];
    red[t] = s;
    __syncthreads();
    #pragma unroll
    for (int off = 512; off > 0; off >>= 1) {
        if (t < off) red[t] += red[t + off];
        __syncthreads();
    }
    double lossTotal = red[0];
    __syncthreads();

    double u = 0.0;
    for (int i = t; i < KC; i += 1024) u += (double)g_used[i];
    red[t] = u;
    __syncthreads();
    #pragma unroll
    for (int off = 512; off > 0; off >>= 1) {
        if (t < off) red[t] += red[t + off];
        __syncthreads();
    }

    if (t == 0) {
        size_t base = (size_t)NROWS * DIM + NROWS;
        out[base]     = (float)(0.25 * lossTotal / ((double)NROWS * (double)DIM));
        out[base + 1] = (float)(red[0] / (double)KC);
    }
}

// ---------------------------------------------------------------------------
extern "C" void kernel_launch(void* const* d_in, const int* in_sizes, int n_in,
                              void* d_out, int out_size) {
    const float* z  = (const float*)d_in[0];   // z_e [32768, 512]
    const float* cb = (const float*)d_in[1];   // codebook [4096, 512]
    if (in_sizes[0] == KC * DIM) {             // defensive: swap if order differs
        z  = (const float*)d_in[1];
        cb = (const float*)d_in[0];
    }
    float* out = (float*)d_out;                // [z_q_st | k | vq_loss | utilization]

    init_kernel<<<(KC + 255) / 256, 256>>>();
    wnorm_kernel<<<KC / 256, 256>>>(cb);
    xnorm_kernel<<<NROWS / 256, 256>>>(z);
    vq_argmin_kernel<<<NROWS / BM, 256>>>(z, cb);
    gather_kernel<<<NROWS, 128>>>(z, cb, out);
    finalize_kernel<<<1, 1024>>>(out);
}